// round 6
// baseline (speedup 1.0000x reference)
#include <cuda_runtime.h>
#include <cstdint>
#include <math.h>

// GRU-style decoder cell via mma.sync tf32; 256x256 CTA tile, 64x64 warp tiles.
//   r = sigmoid(x@Wr^T + hprev@Ur^T + c@Cr^T + br)   -> g_rh = tf32(r*hprev)
//   z = sigmoid(x@Wz^T + hprev@Uz^T + c@Cz^T + bz)   -> g_z
//   h = tanh   (x@Wh^T + g_rh@Uh^T  + c@Ch^T + bh)   -> out = z*h + (1-z)*hprev
// B=8192, IN=1024, H=1024, c:[B,2048]; effective K=4096 per gate.

#define BATCH 8192
#define HID   1024
#define BM 256
#define BN 256
#define BK 32
#define STAGES 3
#define NCHUNK 128       // 4096 / 32

#define A_TILE (BM * BK)            // 8192 floats
#define B_TILE (BN * BK)            // 8192 floats
#define SMEM_BYTES ((STAGES * (A_TILE + B_TILE)) * 4)  // 196608

// ---- scratch ----
__device__ float g_rh[(size_t)BATCH * HID];
__device__ float g_z [(size_t)BATCH * HID];
__device__ float g_xr[(size_t)BATCH * 1024];
__device__ float g_hr[(size_t)BATCH * 1024];
__device__ float g_cr[(size_t)BATCH * 2048];
__device__ float g_wts[(size_t)3 * 4 * 1024 * 1024];

__device__ __forceinline__ void cp16(void* dst_smem, const void* src) {
    uint32_t d = (uint32_t)__cvta_generic_to_shared(dst_smem);
    asm volatile("cp.async.cg.shared.global [%0], [%1], 16;" :: "r"(d), "l"(src));
}
__device__ __forceinline__ void cp_commit() {
    asm volatile("cp.async.commit_group;" ::: "memory");
}
__device__ __forceinline__ void cp_wait1() {
    asm volatile("cp.async.wait_group 1;" ::: "memory");
}
__device__ __forceinline__ uint32_t f2tf32(float x) {
    uint32_t u;
    asm("cvt.rna.tf32.f32 %0, %1;" : "=r"(u) : "f"(x));
    return u;
}
__device__ __forceinline__ void mma_tf32(float* c, uint32_t a0, uint32_t a1,
                                         uint32_t a2, uint32_t a3,
                                         uint32_t b0, uint32_t b1) {
    asm volatile(
        "mma.sync.aligned.m16n8k8.row.col.f32.tf32.tf32.f32 "
        "{%0,%1,%2,%3}, {%4,%5,%6,%7}, {%8,%9}, {%0,%1,%2,%3};"
        : "+f"(c[0]), "+f"(c[1]), "+f"(c[2]), "+f"(c[3])
        : "r"(a0), "r"(a1), "r"(a2), "r"(a3), "r"(b0), "r"(b1));
}
__device__ __forceinline__ float fsigmoid(float v) { return 1.0f / (1.0f + __expf(-v)); }
__device__ __forceinline__ float ftanh(float v) {
    float e = __expf(-2.0f * v);
    return 2.0f / (1.0f + e) - 1.0f;
}

// ---- pre-pass: tf32 rounding ----
__global__ __launch_bounds__(256)
void round_tf32_kernel(const float4* __restrict__ src, float4* __restrict__ dst, int n4)
{
    const int stride = gridDim.x * blockDim.x;
    for (int i = blockIdx.x * blockDim.x + threadIdx.x; i < n4; i += stride) {
        float4 v = src[i];
        v.x = __uint_as_float(f2tf32(v.x));
        v.y = __uint_as_float(f2tf32(v.y));
        v.z = __uint_as_float(f2tf32(v.z));
        v.w = __uint_as_float(f2tf32(v.w));
        dst[i] = v;
    }
}

__global__ __launch_bounds__(512, 1)
void gate_mma_kernel(
    const float* __restrict__ x,
    const float* __restrict__ A1,
    const float* __restrict__ c,
    const float* __restrict__ W0,
    const float* __restrict__ W1,
    const float* __restrict__ W2,
    const float* __restrict__ bias,
    const float* __restrict__ hprev,
    const float* __restrict__ zbuf,
    float* __restrict__ out,
    int mode)
{
    extern __shared__ float sm[];
    float* As = sm;                      // [STAGES][256][32] swizzled
    float* Bs = sm + STAGES * A_TILE;    // [STAGES][256][32] swizzled

    const int tid  = threadIdx.x;
    const int lane = tid & 31;
    const int wid  = tid >> 5;
    const int g    = lane >> 2;   // 0..7
    const int tg   = lane & 3;    // 0..3
    const int wm   = wid >> 2;    // 0..3 -> 64-row slab
    const int wn   = wid & 3;     // 0..3 -> 64-col slab

    const int bm = blockIdx.y * BM;
    const int bn = blockIdx.x * BN;

    // lane-constant swizzled read offsets (floats) per k16-window w:
    const int sw = g & 1;
    const int loff0 = g * 32 + ((((0 ^ sw) << 2) + tg) << 2);
    const int loff1 = g * 32 + ((((1 ^ sw) << 2) + tg) << 2);

    float acc[4][8][4];
#pragma unroll
    for (int i = 0; i < 4; ++i)
#pragma unroll
        for (int j = 0; j < 8; ++j)
#pragma unroll
            for (int k = 0; k < 4; ++k)
                acc[i][j][k] = 0.0f;

    auto issue = [&](int i) {
        const int s = i % STAGES;
        const float* Aseg;
        const float* Wseg;
        int ld, k0;
        if (i < 32)      { Aseg = x;  Wseg = W0; ld = 1024; k0 = i * BK; }
        else if (i < 64) { Aseg = A1; Wseg = W1; ld = 1024; k0 = (i - 32) * BK; }
        else             { Aseg = c;  Wseg = W2; ld = 2048; k0 = (i - 64) * BK; }

        float* ad = As + s * A_TILE;
        float* bd = Bs + s * B_TILE;
        // A: 256 rows x 8 chunks = 2048 cp16; 512 threads -> 4 each
#pragma unroll
        for (int j = 0; j < 4; ++j) {
            const int idx = tid + j * 512;
            const int row = idx >> 3;
            const int ch  = idx & 7;
            const int swc = ch ^ ((row & 1) << 2);
            cp16(ad + row * 32 + (swc << 2),
                 Aseg + (size_t)(bm + row) * ld + k0 + (ch << 2));
        }
        // B: 256 rows x 8 chunks = 2048; 512 threads -> 4 each
#pragma unroll
        for (int j = 0; j < 4; ++j) {
            const int idx = tid + j * 512;
            const int row = idx >> 3;
            const int ch  = idx & 7;
            const int swc = ch ^ ((row & 1) << 2);
            cp16(bd + row * 32 + (swc << 2),
                 Wseg + (size_t)(bn + row) * ld + k0 + (ch << 2));
        }
        cp_commit();
    };

    issue(0); issue(1);

    for (int i = 0; i < NCHUNK; ++i) {
        cp_wait1();
        __syncthreads();
        if (i + 2 < NCHUNK) issue(i + 2);   // writes stage (i+2)%3 == (i-1)%3: readers done

        const int buf = i % STAGES;
        const float* A0 = As + buf * A_TILE + (wm * 64) * 32;
        const float* B0 = Bs + buf * B_TILE + (wn * 64) * 32;

#pragma unroll
        for (int w = 0; w < 2; ++w) {
            const int lo = (w == 0) ? loff0 : loff1;
            float4 bv[8];
#pragma unroll
            for (int nf = 0; nf < 8; ++nf)
                bv[nf] = *(const float4*)(B0 + nf * 256 + lo);
#pragma unroll
            for (int mf = 0; mf < 4; ++mf) {
                const float4 a0v = *(const float4*)(A0 + mf * 512 + lo);
                const float4 a1v = *(const float4*)(A0 + mf * 512 + 256 + lo);
#pragma unroll
                for (int nf = 0; nf < 8; ++nf) {
                    mma_tf32(acc[mf][nf],
                             __float_as_uint(a0v.x), __float_as_uint(a1v.x),
                             __float_as_uint(a0v.y), __float_as_uint(a1v.y),
                             __float_as_uint(bv[nf].x), __float_as_uint(bv[nf].y));
                    mma_tf32(acc[mf][nf],
                             __float_as_uint(a0v.z), __float_as_uint(a1v.z),
                             __float_as_uint(a0v.w), __float_as_uint(a1v.w),
                             __float_as_uint(bv[nf].z), __float_as_uint(bv[nf].w));
                }
            }
        }
    }

    // ---- epilogue ----
#pragma unroll
    for (int mf = 0; mf < 4; ++mf) {
#pragma unroll
        for (int nf = 0; nf < 8; ++nf) {
            const int n = bn + wn * 64 + nf * 8 + 2 * tg;
            const float2 bi = *(const float2*)(bias + n);
#pragma unroll
            for (int half = 0; half < 2; ++half) {
                const int m = bm + wm * 64 + mf * 16 + g + half * 8;
                const size_t idx = (size_t)m * HID + n;
                float v0 = acc[mf][nf][2 * half + 0] + bi.x;
                float v1 = acc[mf][nf][2 * half + 1] + bi.y;
                float2 o;
                if (mode == 0) {
                    const float2 hp = *(const float2*)(hprev + idx);
                    o.x = __uint_as_float(f2tf32(fsigmoid(v0) * hp.x));
                    o.y = __uint_as_float(f2tf32(fsigmoid(v1) * hp.y));
                } else if (mode == 1) {
                    o.x = fsigmoid(v0);
                    o.y = fsigmoid(v1);
                } else {
                    const float2 hp = *(const float2*)(hprev + idx);
                    const float2 zz = *(const float2*)(zbuf + idx);
                    o.x = fmaf(zz.x, ftanh(v0) - hp.x, hp.x);
                    o.y = fmaf(zz.y, ftanh(v1) - hp.y, hp.y);
                }
                *(float2*)(out + idx) = o;
            }
        }
    }
}

static inline void round_pass(const float* src, float* dst, size_t n) {
    const int n4 = (int)(n / 4);
    int blocks = (n4 + 256 * 2 - 1) / (256 * 2);
    if (blocks > 4096) blocks = 4096;
    round_tf32_kernel<<<blocks, 256>>>((const float4*)src, (float4*)dst, n4);
}

extern "C" void kernel_launch(void* const* d_in, const int* in_sizes, int n_in,
                              void* d_out, int out_size)
{
    const float* x     = (const float*)d_in[0];
    const float* hprev = (const float*)d_in[1];
    const float* c     = (const float*)d_in[2];
    const float* Wh    = (const float*)d_in[3];
    const float* Wz    = (const float*)d_in[4];
    const float* Wr    = (const float*)d_in[5];
    const float* Uh    = (const float*)d_in[6];
    const float* Uz    = (const float*)d_in[7];
    const float* Ur    = (const float*)d_in[8];
    const float* Ch    = (const float*)d_in[9];
    const float* Cz    = (const float*)d_in[10];
    const float* Cr    = (const float*)d_in[11];
    const float* bh    = (const float*)d_in[12];
    const float* bz    = (const float*)d_in[13];
    const float* br    = (const float*)d_in[14];
    float* out = (float*)d_out;

    float *rh_p, *z_p, *xr_p, *hr_p, *cr_p, *wts_p;
    cudaGetSymbolAddress((void**)&rh_p,  g_rh);
    cudaGetSymbolAddress((void**)&z_p,   g_z);
    cudaGetSymbolAddress((void**)&xr_p,  g_xr);
    cudaGetSymbolAddress((void**)&hr_p,  g_hr);
    cudaGetSymbolAddress((void**)&cr_p,  g_cr);
    cudaGetSymbolAddress((void**)&wts_p, g_wts);

    const size_t M1 = (size_t)1024 * 1024;
    float* wr_W = wts_p + 0 * 4 * M1; float* wr_U = wr_W + M1; float* wr_C = wr_U + M1;
    float* wz_W = wts_p + 1 * 4 * M1; float* wz_U = wz_W + M1; float* wz_C = wz_U + M1;
    float* wh_W = wts_p + 2 * 4 * M1; float* wh_U = wh_W + M1; float* wh_C = wh_U + M1;

    round_pass(x,     xr_p, (size_t)BATCH * 1024);
    round_pass(hprev, hr_p, (size_t)BATCH * 1024);
    round_pass(c,     cr_p, (size_t)BATCH * 2048);
    round_pass(Wr, wr_W, M1);  round_pass(Ur, wr_U, M1);  round_pass(Cr, wr_C, 2 * M1);
    round_pass(Wz, wz_W, M1);  round_pass(Uz, wz_U, M1);  round_pass(Cz, wz_C, 2 * M1);
    round_pass(Wh, wh_W, M1);  round_pass(Uh, wh_U, M1);  round_pass(Ch, wh_C, 2 * M1);

    cudaFuncSetAttribute(gate_mma_kernel,
                         cudaFuncAttributeMaxDynamicSharedMemorySize, SMEM_BYTES);

    const dim3 grid(HID / BN, BATCH / BM);  // (4, 32) = 128 CTAs -> single wave
    const dim3 block(512);

    gate_mma_kernel<<<grid, block, SMEM_BYTES>>>(
        xr_p, hr_p, cr_p, wr_W, wr_U, wr_C, br, hprev, nullptr, rh_p, 0);
    gate_mma_kernel<<<grid, block, SMEM_BYTES>>>(
        xr_p, hr_p, cr_p, wz_W, wz_U, wz_C, bz, hprev, nullptr, z_p, 1);
    gate_mma_kernel<<<grid, block, SMEM_BYTES>>>(
        xr_p, rh_p, cr_p, wh_W, wh_U, wh_C, bh, hprev, z_p, out, 2);
}

// round 7
// speedup vs baseline: 3.0881x; 3.0881x over previous
#include <cuda_runtime.h>
#include <cstdint>
#include <math.h>

// GRU-style decoder cell via mma.sync tf32; 128x128 CTA tile, 2 CTAs/SM.
//   r = sigmoid(x@Wr^T + hprev@Ur^T + c@Cr^T + br)   -> g_rh = tf32(r*hprev)
//   z = sigmoid(x@Wz^T + hprev@Uz^T + c@Cz^T + bz)   -> g_z
//   h = tanh   (x@Wh^T + g_rh@Uh^T  + c@Ch^T + bh)   -> out = z*h + (1-z)*hprev
// B=8192, IN=1024, H=1024, c:[B,2048]; effective K=4096 per gate.

#define BATCH 8192
#define HID   1024
#define BM 128
#define BN 128
#define BK 32
#define STAGES 3
#define NCHUNK 128       // 4096 / 32

#define A_TILE (BM * BK)            // 4096 floats
#define B_TILE (BN * BK)            // 4096 floats
#define SMEM_BYTES ((STAGES * (A_TILE + B_TILE)) * 4)  // 98304 -> 2 CTAs/SM

// ---- scratch ----
__device__ float g_rh[(size_t)BATCH * HID];
__device__ float g_z [(size_t)BATCH * HID];
__device__ float g_xr[(size_t)BATCH * 1024];
__device__ float g_hr[(size_t)BATCH * 1024];
__device__ float g_cr[(size_t)BATCH * 2048];
__device__ float g_wts[(size_t)3 * 4 * 1024 * 1024];

__device__ __forceinline__ void cp16(void* dst_smem, const void* src) {
    uint32_t d = (uint32_t)__cvta_generic_to_shared(dst_smem);
    asm volatile("cp.async.cg.shared.global [%0], [%1], 16;" :: "r"(d), "l"(src));
}
__device__ __forceinline__ void cp_commit() {
    asm volatile("cp.async.commit_group;" ::: "memory");
}
__device__ __forceinline__ void cp_wait1() {
    asm volatile("cp.async.wait_group 1;" ::: "memory");
}
__device__ __forceinline__ uint32_t f2tf32(float x) {
    uint32_t u;
    asm("cvt.rna.tf32.f32 %0, %1;" : "=r"(u) : "f"(x));
    return u;
}
__device__ __forceinline__ void mma_tf32(float* c, uint32_t a0, uint32_t a1,
                                         uint32_t a2, uint32_t a3,
                                         uint32_t b0, uint32_t b1) {
    asm volatile(
        "mma.sync.aligned.m16n8k8.row.col.f32.tf32.tf32.f32 "
        "{%0,%1,%2,%3}, {%4,%5,%6,%7}, {%8,%9}, {%0,%1,%2,%3};"
        : "+f"(c[0]), "+f"(c[1]), "+f"(c[2]), "+f"(c[3])
        : "r"(a0), "r"(a1), "r"(a2), "r"(a3), "r"(b0), "r"(b1));
}
__device__ __forceinline__ float fsigmoid(float v) { return 1.0f / (1.0f + __expf(-v)); }
__device__ __forceinline__ float ftanh(float v) {
    float e = __expf(-2.0f * v);
    return 2.0f / (1.0f + e) - 1.0f;
}

// ---- pre-pass: tf32 rounding ----
__global__ __launch_bounds__(256)
void round_tf32_kernel(const float4* __restrict__ src, float4* __restrict__ dst, int n4)
{
    const int stride = gridDim.x * blockDim.x;
    for (int i = blockIdx.x * blockDim.x + threadIdx.x; i < n4; i += stride) {
        float4 v = src[i];
        v.x = __uint_as_float(f2tf32(v.x));
        v.y = __uint_as_float(f2tf32(v.y));
        v.z = __uint_as_float(f2tf32(v.z));
        v.w = __uint_as_float(f2tf32(v.w));
        dst[i] = v;
    }
}

__global__ __launch_bounds__(256, 2)
void gate_mma_kernel(
    const float* __restrict__ x,
    const float* __restrict__ A1,
    const float* __restrict__ c,
    const float* __restrict__ W0,
    const float* __restrict__ W1,
    const float* __restrict__ W2,
    const float* __restrict__ bias,
    const float* __restrict__ hprev,
    const float* __restrict__ zbuf,
    float* __restrict__ out,
    int mode)
{
    extern __shared__ float sm[];
    float* As = sm;                      // [STAGES][128][32] swizzled
    float* Bs = sm + STAGES * A_TILE;    // [STAGES][128][32] swizzled

    const int tid  = threadIdx.x;
    const int lane = tid & 31;
    const int wid  = tid >> 5;    // 0..7
    const int g    = lane >> 2;   // 0..7
    const int tg   = lane & 3;    // 0..3
    const int wm   = wid >> 2;    // 0..1 -> 64-row slab
    const int wn   = wid & 3;     // 0..3 -> 32-col slab

    const int bm = blockIdx.y * BM;
    const int bn = blockIdx.x * BN;

    // lane-constant swizzled read offsets (floats) per k16-window
    const int sw = g & 1;
    const int loff0 = g * 32 + ((((0 ^ sw) << 2) + tg) << 2);
    const int loff1 = g * 32 + ((((1 ^ sw) << 2) + tg) << 2);

    float acc[4][4][4];
#pragma unroll
    for (int i = 0; i < 4; ++i)
#pragma unroll
        for (int j = 0; j < 4; ++j)
#pragma unroll
            for (int k = 0; k < 4; ++k)
                acc[i][j][k] = 0.0f;

    auto issue = [&](int i) {
        const int s = i % STAGES;
        const float* Aseg;
        const float* Wseg;
        int ld, k0;
        if (i < 32)      { Aseg = x;  Wseg = W0; ld = 1024; k0 = i * BK; }
        else if (i < 64) { Aseg = A1; Wseg = W1; ld = 1024; k0 = (i - 32) * BK; }
        else             { Aseg = c;  Wseg = W2; ld = 2048; k0 = (i - 64) * BK; }

        float* ad = As + s * A_TILE;
        float* bd = Bs + s * B_TILE;
        // A: 128 rows x 8 chunks = 1024 cp16; 256 threads -> 4 each
#pragma unroll
        for (int j = 0; j < 4; ++j) {
            const int idx = tid + j * 256;
            const int row = idx >> 3;
            const int ch  = idx & 7;
            const int swc = ch ^ ((row & 1) << 2);
            cp16(ad + row * 32 + (swc << 2),
                 Aseg + (size_t)(bm + row) * ld + k0 + (ch << 2));
        }
        // B: 128 rows x 8 chunks = 1024; 256 threads -> 4 each
#pragma unroll
        for (int j = 0; j < 4; ++j) {
            const int idx = tid + j * 256;
            const int row = idx >> 3;
            const int ch  = idx & 7;
            const int swc = ch ^ ((row & 1) << 2);
            cp16(bd + row * 32 + (swc << 2),
                 Wseg + (size_t)(bn + row) * ld + k0 + (ch << 2));
        }
        cp_commit();
    };

    issue(0); issue(1);

    for (int i = 0; i < NCHUNK; ++i) {
        cp_wait1();
        __syncthreads();
        if (i + 2 < NCHUNK) issue(i + 2);   // writes stage (i+2)%3 == (i-1)%3: readers done

        const int buf = i % STAGES;
        const float* A0 = As + buf * A_TILE + (wm * 64) * 32;
        const float* B0 = Bs + buf * B_TILE + (wn * 32) * 32;

#pragma unroll
        for (int w = 0; w < 2; ++w) {
            const int lo = (w == 0) ? loff0 : loff1;
            float4 bv[4];
#pragma unroll
            for (int nf = 0; nf < 4; ++nf)
                bv[nf] = *(const float4*)(B0 + nf * 256 + lo);
#pragma unroll
            for (int mf = 0; mf < 4; ++mf) {
                const float4 a0v = *(const float4*)(A0 + mf * 512 + lo);
                const float4 a1v = *(const float4*)(A0 + mf * 512 + 256 + lo);
                // window-half 1 across all nf (no back-to-back RAW per acc)
#pragma unroll
                for (int nf = 0; nf < 4; ++nf)
                    mma_tf32(acc[mf][nf],
                             __float_as_uint(a0v.x), __float_as_uint(a1v.x),
                             __float_as_uint(a0v.y), __float_as_uint(a1v.y),
                             __float_as_uint(bv[nf].x), __float_as_uint(bv[nf].y));
                // window-half 2
#pragma unroll
                for (int nf = 0; nf < 4; ++nf)
                    mma_tf32(acc[mf][nf],
                             __float_as_uint(a0v.z), __float_as_uint(a1v.z),
                             __float_as_uint(a0v.w), __float_as_uint(a1v.w),
                             __float_as_uint(bv[nf].z), __float_as_uint(bv[nf].w));
            }
        }
    }

    // ---- epilogue ----
#pragma unroll
    for (int mf = 0; mf < 4; ++mf) {
#pragma unroll
        for (int nf = 0; nf < 4; ++nf) {
            const int n = bn + wn * 32 + nf * 8 + 2 * tg;
            const float2 bi = *(const float2*)(bias + n);
#pragma unroll
            for (int half = 0; half < 2; ++half) {
                const int m = bm + wm * 64 + mf * 16 + g + half * 8;
                const size_t idx = (size_t)m * HID + n;
                float v0 = acc[mf][nf][2 * half + 0] + bi.x;
                float v1 = acc[mf][nf][2 * half + 1] + bi.y;
                float2 o;
                if (mode == 0) {
                    const float2 hp = *(const float2*)(hprev + idx);
                    o.x = __uint_as_float(f2tf32(fsigmoid(v0) * hp.x));
                    o.y = __uint_as_float(f2tf32(fsigmoid(v1) * hp.y));
                } else if (mode == 1) {
                    o.x = fsigmoid(v0);
                    o.y = fsigmoid(v1);
                } else {
                    const float2 hp = *(const float2*)(hprev + idx);
                    const float2 zz = *(const float2*)(zbuf + idx);
                    o.x = fmaf(zz.x, ftanh(v0) - hp.x, hp.x);
                    o.y = fmaf(zz.y, ftanh(v1) - hp.y, hp.y);
                }
                *(float2*)(out + idx) = o;
            }
        }
    }
}

static inline void round_pass(const float* src, float* dst, size_t n) {
    const int n4 = (int)(n / 4);
    int blocks = (n4 + 256 * 2 - 1) / (256 * 2);
    if (blocks > 4096) blocks = 4096;
    round_tf32_kernel<<<blocks, 256>>>((const float4*)src, (float4*)dst, n4);
}

extern "C" void kernel_launch(void* const* d_in, const int* in_sizes, int n_in,
                              void* d_out, int out_size)
{
    const float* x     = (const float*)d_in[0];
    const float* hprev = (const float*)d_in[1];
    const float* c     = (const float*)d_in[2];
    const float* Wh    = (const float*)d_in[3];
    const float* Wz    = (const float*)d_in[4];
    const float* Wr    = (const float*)d_in[5];
    const float* Uh    = (const float*)d_in[6];
    const float* Uz    = (const float*)d_in[7];
    const float* Ur    = (const float*)d_in[8];
    const float* Ch    = (const float*)d_in[9];
    const float* Cz    = (const float*)d_in[10];
    const float* Cr    = (const float*)d_in[11];
    const float* bh    = (const float*)d_in[12];
    const float* bz    = (const float*)d_in[13];
    const float* br    = (const float*)d_in[14];
    float* out = (float*)d_out;

    float *rh_p, *z_p, *xr_p, *hr_p, *cr_p, *wts_p;
    cudaGetSymbolAddress((void**)&rh_p,  g_rh);
    cudaGetSymbolAddress((void**)&z_p,   g_z);
    cudaGetSymbolAddress((void**)&xr_p,  g_xr);
    cudaGetSymbolAddress((void**)&hr_p,  g_hr);
    cudaGetSymbolAddress((void**)&cr_p,  g_cr);
    cudaGetSymbolAddress((void**)&wts_p, g_wts);

    const size_t M1 = (size_t)1024 * 1024;
    float* wr_W = wts_p + 0 * 4 * M1; float* wr_U = wr_W + M1; float* wr_C = wr_U + M1;
    float* wz_W = wts_p + 1 * 4 * M1; float* wz_U = wz_W + M1; float* wz_C = wz_U + M1;
    float* wh_W = wts_p + 2 * 4 * M1; float* wh_U = wh_W + M1; float* wh_C = wh_U + M1;

    round_pass(x,     xr_p, (size_t)BATCH * 1024);
    round_pass(hprev, hr_p, (size_t)BATCH * 1024);
    round_pass(c,     cr_p, (size_t)BATCH * 2048);
    round_pass(Wr, wr_W, M1);  round_pass(Ur, wr_U, M1);  round_pass(Cr, wr_C, 2 * M1);
    round_pass(Wz, wz_W, M1);  round_pass(Uz, wz_U, M1);  round_pass(Cz, wz_C, 2 * M1);
    round_pass(Wh, wh_W, M1);  round_pass(Uh, wh_U, M1);  round_pass(Ch, wh_C, 2 * M1);

    cudaFuncSetAttribute(gate_mma_kernel,
                         cudaFuncAttributeMaxDynamicSharedMemorySize, SMEM_BYTES);

    const dim3 grid(HID / BN, BATCH / BM);  // (8, 64) = 512 CTAs, 2/SM
    const dim3 block(256);

    gate_mma_kernel<<<grid, block, SMEM_BYTES>>>(
        xr_p, hr_p, cr_p, wr_W, wr_U, wr_C, br, hprev, nullptr, rh_p, 0);
    gate_mma_kernel<<<grid, block, SMEM_BYTES>>>(
        xr_p, hr_p, cr_p, wz_W, wz_U, wz_C, bz, hprev, nullptr, z_p, 1);
    gate_mma_kernel<<<grid, block, SMEM_BYTES>>>(
        xr_p, rh_p, cr_p, wh_W, wh_U, wh_C, bh, hprev, z_p, out, 2);
}

// round 10
// speedup vs baseline: 5.7724x; 1.8692x over previous
#include <cuda_runtime.h>
#include <cuda_fp16.h>
#include <cstdint>
#include <math.h>

// GRU-style decoder cell via mma.sync fp16 (m16n8k16, fp32 accum).
//   r = sigmoid(x@Wr^T + hprev@Ur^T + c@Cr^T + br)   -> g_rh2 = fp16(r*hprev)
//   z = sigmoid(x@Wz^T + hprev@Uz^T + c@Cz^T + bz)   -> g_z (fp32)
//   h = tanh   (x@Wh^T + g_rh2@Uh^T + c@Ch^T + bh)   -> out = z*h + (1-z)*hprev
// B=8192, IN=1024, H=1024, c:[B,2048]; effective K=4096 per gate.

#define BATCH 8192
#define HID   1024
#define BM 128
#define BN 128
#define BK 32            // halves per chunk = 64B per row
#define STAGES 4
#define NCHUNK 128       // 4096 / 32

#define A_TILE (BM * BK)            // halves (4096)
#define B_TILE (BN * BK)
#define SMEM_BYTES ((STAGES * (A_TILE + B_TILE)) * 2)  // 65536 -> 2 CTAs/SM

// ---- scratch (allocation-free) ----
__device__ __half g_x2 [(size_t)BATCH * 1024];
__device__ __half g_h2 [(size_t)BATCH * 1024];
__device__ __half g_c2 [(size_t)BATCH * 2048];
__device__ __half g_rh2[(size_t)BATCH * HID];
__device__ float  g_z  [(size_t)BATCH * HID];
__device__ __half g_w2 [(size_t)3 * 4 * 1024 * 1024];  // per gate: W|U|C(2M)

__device__ __forceinline__ void cp16(void* dst_smem, const void* src) {
    uint32_t d = (uint32_t)__cvta_generic_to_shared(dst_smem);
    asm volatile("cp.async.cg.shared.global [%0], [%1], 16;" :: "r"(d), "l"(src));
}
__device__ __forceinline__ void cp_commit() {
    asm volatile("cp.async.commit_group;" ::: "memory");
}
__device__ __forceinline__ void cp_wait2() {
    asm volatile("cp.async.wait_group 2;" ::: "memory");
}
__device__ __forceinline__ uint32_t h2_bits(__half2 h) {
    return *reinterpret_cast<uint32_t*>(&h);
}
__device__ __forceinline__ void mma_f16(float* c, uint32_t a0, uint32_t a1,
                                        uint32_t a2, uint32_t a3,
                                        uint32_t b0, uint32_t b1) {
    asm volatile(
        "mma.sync.aligned.m16n8k16.row.col.f32.f16.f16.f32 "
        "{%0,%1,%2,%3}, {%4,%5,%6,%7}, {%8,%9}, {%0,%1,%2,%3};"
        : "+f"(c[0]), "+f"(c[1]), "+f"(c[2]), "+f"(c[3])
        : "r"(a0), "r"(a1), "r"(a2), "r"(a3), "r"(b0), "r"(b1));
}
__device__ __forceinline__ float fsigmoid(float v) { return 1.0f / (1.0f + __expf(-v)); }
__device__ __forceinline__ float ftanh(float v) {
    float e = __expf(-2.0f * v);
    return 2.0f / (1.0f + e) - 1.0f;
}

// ---- pre-pass: fp32 -> fp16 ----
__global__ __launch_bounds__(256)
void cvt_f16_kernel(const float4* __restrict__ src, uint2* __restrict__ dst, int n4)
{
    const int stride = gridDim.x * blockDim.x;
    for (int i = blockIdx.x * blockDim.x + threadIdx.x; i < n4; i += stride) {
        const float4 v = src[i];
        uint2 o;
        o.x = h2_bits(__floats2half2_rn(v.x, v.y));
        o.y = h2_bits(__floats2half2_rn(v.z, v.w));
        dst[i] = o;
    }
}

__global__ __launch_bounds__(256, 2)
void gate_mma_kernel(
    const __half* __restrict__ x,     // [B,1024]
    const __half* __restrict__ A1,    // [B,1024] (g_h2 or g_rh2)
    const __half* __restrict__ c,     // [B,2048]
    const __half* __restrict__ W0,    // [1024,1024]
    const __half* __restrict__ W1,    // [1024,1024]
    const __half* __restrict__ W2,    // [1024,2048]
    const float* __restrict__ bias,
    const float* __restrict__ hprev,
    const float* __restrict__ zbuf,
    void* __restrict__ outv,          // mode 0: __half*, else float*
    int mode)
{
    extern __shared__ __half sh[];
    __half* As = sh;                       // [STAGES][128][32] swizzled (16B-chunk XOR)
    __half* Bs = sh + STAGES * A_TILE;

    const int tid  = threadIdx.x;
    const int lane = tid & 31;
    const int wid  = tid >> 5;    // 0..7
    const int g    = lane >> 2;   // 0..7
    const int tg   = lane & 3;    // 0..3
    const int wm   = wid >> 2;    // 0..1 -> 64-row slab
    const int wn   = wid & 3;     // 0..3 -> 32-col slab

    const int bm = blockIdx.y * BM;
    const int bn = blockIdx.x * BN;

    // lane-constant swizzled chunk offset (halves): frag rows have row&3 == g&3
    const int loff = ((tg ^ (g & 3)) << 3);

    float acc[4][4][4];
#pragma unroll
    for (int i = 0; i < 4; ++i)
#pragma unroll
        for (int j = 0; j < 4; ++j)
#pragma unroll
            for (int k = 0; k < 4; ++k)
                acc[i][j][k] = 0.0f;

    auto issue = [&](int i) {
        const int s = i & 3;
        const __half* Aseg;
        const __half* Wseg;
        int ld, k0;
        if (i < 32)      { Aseg = x;  Wseg = W0; ld = 1024; k0 = i * BK; }
        else if (i < 64) { Aseg = A1; Wseg = W1; ld = 1024; k0 = (i - 32) * BK; }
        else             { Aseg = c;  Wseg = W2; ld = 2048; k0 = (i - 64) * BK; }

        __half* ad = As + s * A_TILE;
        __half* bd = Bs + s * B_TILE;
        // A: 128 rows x 4 chunks(16B) = 512 cp16; 256 threads -> 2 each
#pragma unroll
        for (int j = 0; j < 2; ++j) {
            const int idx = tid + j * 256;
            const int row = idx >> 2;
            const int ch  = idx & 3;
            const int swc = ch ^ (row & 3);
            cp16(ad + row * 32 + (swc << 3),
                 Aseg + (size_t)(bm + row) * ld + k0 + (ch << 3));
        }
        // B: 128 rows x 4 chunks = 512; 256 threads -> 2 each
#pragma unroll
        for (int j = 0; j < 2; ++j) {
            const int idx = tid + j * 256;
            const int row = idx >> 2;
            const int ch  = idx & 3;
            const int swc = ch ^ (row & 3);
            cp16(bd + row * 32 + (swc << 3),
                 Wseg + (size_t)(bn + row) * ld + k0 + (ch << 3));
        }
        cp_commit();
    };

    issue(0); issue(1); issue(2);

    for (int i = 0; i < NCHUNK; ++i) {
        cp_wait2();
        __syncthreads();
        if (i + 3 < NCHUNK) issue(i + 3);   // writes stage (i-1)&3: readers done

        const int buf = i & 3;
        const __half* A0 = As + buf * A_TILE + (wm * 64) * 32;
        const __half* B0 = Bs + buf * B_TILE + (wn * 32) * 32;

        // B frags: one uint4 per nf covers both k16 windows (k-run [8tg,8tg+8))
        uint4 bv[4];
#pragma unroll
        for (int nf = 0; nf < 4; ++nf)
            bv[nf] = *(const uint4*)(B0 + (nf * 8 + g) * 32 + loff);

#pragma unroll
        for (int mf = 0; mf < 4; ++mf) {
            const uint4 a0 = *(const uint4*)(A0 + (mf * 16 + g) * 32 + loff);
            const uint4 a1 = *(const uint4*)(A0 + (mf * 16 + g + 8) * 32 + loff);
            // window 0: lane tg owns k {8tg,8tg+1} (low) and {8tg+2,8tg+3} (high)
#pragma unroll
            for (int nf = 0; nf < 4; ++nf)
                mma_f16(acc[mf][nf], a0.x, a1.x, a0.y, a1.y, bv[nf].x, bv[nf].y);
            // window 1: k {8tg+4,8tg+5} / {8tg+6,8tg+7}
#pragma unroll
            for (int nf = 0; nf < 4; ++nf)
                mma_f16(acc[mf][nf], a0.z, a1.z, a0.w, a1.w, bv[nf].z, bv[nf].w);
        }
    }

    // ---- epilogue ----
#pragma unroll
    for (int mf = 0; mf < 4; ++mf) {
#pragma unroll
        for (int nf = 0; nf < 4; ++nf) {
            const int n = bn + wn * 32 + nf * 8 + 2 * tg;
            const float2 bi = *(const float2*)(bias + n);
#pragma unroll
            for (int half = 0; half < 2; ++half) {
                const int m = bm + wm * 64 + mf * 16 + g + half * 8;
                const size_t idx = (size_t)m * HID + n;
                float v0 = acc[mf][nf][2 * half + 0] + bi.x;
                float v1 = acc[mf][nf][2 * half + 1] + bi.y;
                if (mode == 0) {
                    const float2 hp = *(const float2*)(hprev + idx);
                    __half2* o = (__half2*)((__half*)outv + idx);
                    *o = __floats2half2_rn(fsigmoid(v0) * hp.x, fsigmoid(v1) * hp.y);
                } else if (mode == 1) {
                    float2 o;
                    o.x = fsigmoid(v0);
                    o.y = fsigmoid(v1);
                    *(float2*)((float*)outv + idx) = o;
                } else {
                    const float2 hp = *(const float2*)(hprev + idx);
                    const float2 zz = *(const float2*)(zbuf + idx);
                    float2 o;
                    o.x = fmaf(zz.x, ftanh(v0) - hp.x, hp.x);
                    o.y = fmaf(zz.y, ftanh(v1) - hp.y, hp.y);
                    *(float2*)((float*)outv + idx) = o;
                }
            }
        }
    }
}

static inline void cvt_pass(const float* src, __half* dst, size_t n) {
    const int n4 = (int)(n / 4);
    int blocks = (n4 + 256 * 2 - 1) / (256 * 2);
    if (blocks > 4096) blocks = 4096;
    cvt_f16_kernel<<<blocks, 256>>>((const float4*)src, (uint2*)dst, n4);
}

extern "C" void kernel_launch(void* const* d_in, const int* in_sizes, int n_in,
                              void* d_out, int out_size)
{
    const float* x     = (const float*)d_in[0];
    const float* hprev = (const float*)d_in[1];
    const float* c     = (const float*)d_in[2];
    const float* Wh    = (const float*)d_in[3];
    const float* Wz    = (const float*)d_in[4];
    const float* Wr    = (const float*)d_in[5];
    const float* Uh    = (const float*)d_in[6];
    const float* Uz    = (const float*)d_in[7];
    const float* Ur    = (const float*)d_in[8];
    const float* Ch    = (const float*)d_in[9];
    const float* Cz    = (const float*)d_in[10];
    const float* Cr    = (const float*)d_in[11];
    const float* bh    = (const float*)d_in[12];
    const float* bz    = (const float*)d_in[13];
    const float* br    = (const float*)d_in[14];
    float* out = (float*)d_out;

    __half *x2, *h2, *c2, *rh2, *w2;
    float *z_p;
    cudaGetSymbolAddress((void**)&x2,  g_x2);
    cudaGetSymbolAddress((void**)&h2,  g_h2);
    cudaGetSymbolAddress((void**)&c2,  g_c2);
    cudaGetSymbolAddress((void**)&rh2, g_rh2);
    cudaGetSymbolAddress((void**)&z_p, g_z);
    cudaGetSymbolAddress((void**)&w2,  g_w2);

    const size_t M1 = (size_t)1024 * 1024;
    __half* wr_W = w2 + 0 * 4 * M1; __half* wr_U = wr_W + M1; __half* wr_C = wr_U + M1;
    __half* wz_W = w2 + 1 * 4 * M1; __half* wz_U = wz_W + M1; __half* wz_C = wz_U + M1;
    __half* wh_W = w2 + 2 * 4 * M1; __half* wh_U = wh_W + M1; __half* wh_C = wh_U + M1;

    cvt_pass(x,     x2, (size_t)BATCH * 1024);
    cvt_pass(hprev, h2, (size_t)BATCH * 1024);
    cvt_pass(c,     c2, (size_t)BATCH * 2048);
    cvt_pass(Wr, wr_W, M1);  cvt_pass(Ur, wr_U, M1);  cvt_pass(Cr, wr_C, 2 * M1);
    cvt_pass(Wz, wz_W, M1);  cvt_pass(Uz, wz_U, M1);  cvt_pass(Cz, wz_C, 2 * M1);
    cvt_pass(Wh, wh_W, M1);  cvt_pass(Uh, wh_U, M1);  cvt_pass(Ch, wh_C, 2 * M1);

    cudaFuncSetAttribute(gate_mma_kernel,
                         cudaFuncAttributeMaxDynamicSharedMemorySize, SMEM_BYTES);

    const dim3 grid(HID / BN, BATCH / BM);  // (8, 64) = 512 CTAs, 2/SM
    const dim3 block(256);

    // r gate -> g_rh2 = fp16(sigmoid(.) * hprev)
    gate_mma_kernel<<<grid, block, SMEM_BYTES>>>(
        x2, h2, c2, wr_W, wr_U, wr_C, br, hprev, nullptr, rh2, 0);
    // z gate -> g_z
    gate_mma_kernel<<<grid, block, SMEM_BYTES>>>(
        x2, h2, c2, wz_W, wz_U, wz_C, bz, hprev, nullptr, z_p, 1);
    // h gate -> out
    gate_mma_kernel<<<grid, block, SMEM_BYTES>>>(
        x2, rh2, c2, wh_W, wh_U, wh_C, bh, hprev, z_p, out, 2);
}

// round 12
// speedup vs baseline: 6.3053x; 1.0923x over previous
#include <cuda_runtime.h>
#include <cuda_fp16.h>
#include <cstdint>
#include <math.h>

// GRU-style decoder cell via mma.sync fp16 (m16n8k16, fp32 accum).
// r,z fused into one N=2048 GEMM (stacked weights); h separate.
//   r = sigmoid(x@Wr^T + hprev@Ur^T + c@Cr^T + br)   -> g_rh2 = fp16(r*hprev)
//   z = sigmoid(x@Wz^T + hprev@Uz^T + c@Cz^T + bz)   -> g_z (fp32)
//   h = tanh   (x@Wh^T + g_rh2@Uh^T + c@Ch^T + bh)   -> out = z*h + (1-z)*hprev
// B=8192, IN=1024, H=1024, c:[B,2048]; effective K=4096 per gate.

#define BATCH 8192
#define HID   1024
#define BM 128
#define BN 128
#define BK 32            // halves per chunk = 64B per row
#define STAGES 4
#define NCHUNK 128       // 4096 / 32

#define A_TILE (BM * BK)
#define B_TILE (BN * BK)
#define SMEM_BYTES ((STAGES * (A_TILE + B_TILE)) * 2)  // 65536 -> 2 CTAs/SM

// ---- scratch (allocation-free) ----
__device__ __half g_x2 [(size_t)BATCH * 1024];
__device__ __half g_h2 [(size_t)BATCH * 1024];
__device__ __half g_c2 [(size_t)BATCH * 2048];
__device__ __half g_rh2[(size_t)BATCH * HID];
__device__ float  g_z  [(size_t)BATCH * HID];
// layout: rzW[2M] rzU[2M] rzC[4M] hW[1M] hU[1M] hC[2M]  (halves)
__device__ __half g_w2 [(size_t)12 * 1024 * 1024];

__device__ __forceinline__ void cp16(void* dst_smem, const void* src) {
    uint32_t d = (uint32_t)__cvta_generic_to_shared(dst_smem);
    asm volatile("cp.async.cg.shared.global [%0], [%1], 16;" :: "r"(d), "l"(src));
}
__device__ __forceinline__ void cp_commit() {
    asm volatile("cp.async.commit_group;" ::: "memory");
}
__device__ __forceinline__ void cp_wait2() {
    asm volatile("cp.async.wait_group 2;" ::: "memory");
}
__device__ __forceinline__ uint32_t h2_bits(__half2 h) {
    return *reinterpret_cast<uint32_t*>(&h);
}
__device__ __forceinline__ void mma_f16(float* c, uint32_t a0, uint32_t a1,
                                        uint32_t a2, uint32_t a3,
                                        uint32_t b0, uint32_t b1) {
    asm volatile(
        "mma.sync.aligned.m16n8k16.row.col.f32.f16.f16.f32 "
        "{%0,%1,%2,%3}, {%4,%5,%6,%7}, {%8,%9}, {%0,%1,%2,%3};"
        : "+f"(c[0]), "+f"(c[1]), "+f"(c[2]), "+f"(c[3])
        : "r"(a0), "r"(a1), "r"(a2), "r"(a3), "r"(b0), "r"(b1));
}
__device__ __forceinline__ float fsigmoid(float v) { return 1.0f / (1.0f + __expf(-v)); }
__device__ __forceinline__ float ftanh(float v) {
    float e = __expf(-2.0f * v);
    return 2.0f / (1.0f + e) - 1.0f;
}

// ---- consolidated fp32 -> fp16 conversion over 12 segments ----
#define NSEG 12
struct CvtSegs {
    const float4* src[NSEG];
    uint2*        dst[NSEG];
    int           off[NSEG + 1];   // prefix offsets in float4 units
};

__global__ __launch_bounds__(256)
void cvt_all_kernel(const __grid_constant__ CvtSegs segs)
{
    const int total  = segs.off[NSEG];
    const int stride = gridDim.x * blockDim.x;
    for (int i = blockIdx.x * blockDim.x + threadIdx.x; i < total; i += stride) {
        int s = 0;
#pragma unroll
        for (int k = 1; k < NSEG; ++k)
            if (i >= segs.off[k]) s = k;
        const int j = i - segs.off[s];
        const float4 v = segs.src[s][j];
        uint2 o;
        o.x = h2_bits(__floats2half2_rn(v.x, v.y));
        o.y = h2_bits(__floats2half2_rn(v.z, v.w));
        segs.dst[s][j] = o;
    }
}

// mode 0: fused rz (bn<1024 -> rh2 fp16; else -> z fp32)
// mode 2: final h   (out = z*tanh + (1-z)*hprev)
__global__ __launch_bounds__(256, 2)
void gate_mma_kernel(
    const __half* __restrict__ x,
    const __half* __restrict__ A1,
    const __half* __restrict__ c,
    const __half* __restrict__ W0,
    const __half* __restrict__ W1,
    const __half* __restrict__ W2,
    const float* __restrict__ bias_a,   // r-bias (mode0) / h-bias (mode2)
    const float* __restrict__ bias_b,   // z-bias (mode0)
    const float* __restrict__ hprev,
    const float* __restrict__ zbuf,     // mode2
    __half* __restrict__ out_h,         // mode0: rh2
    float* __restrict__ out_f,          // mode0: z / mode2: out
    int mode)
{
    extern __shared__ __half sh[];
    __half* As = sh;
    __half* Bs = sh + STAGES * A_TILE;

    const int tid  = threadIdx.x;
    const int lane = tid & 31;
    const int wid  = tid >> 5;
    const int g    = lane >> 2;
    const int tg   = lane & 3;
    const int wm   = wid >> 2;
    const int wn   = wid & 3;

    const int bm = blockIdx.y * BM;
    const int bn = blockIdx.x * BN;

    const int loff = ((tg ^ (g & 3)) << 3);

    float acc[4][4][4];
#pragma unroll
    for (int i = 0; i < 4; ++i)
#pragma unroll
        for (int j = 0; j < 4; ++j)
#pragma unroll
            for (int k = 0; k < 4; ++k)
                acc[i][j][k] = 0.0f;

    auto issue = [&](int i) {
        const int s = i & 3;
        const __half* Aseg;
        const __half* Wseg;
        int ld, k0;
        if (i < 32)      { Aseg = x;  Wseg = W0; ld = 1024; k0 = i * BK; }
        else if (i < 64) { Aseg = A1; Wseg = W1; ld = 1024; k0 = (i - 32) * BK; }
        else             { Aseg = c;  Wseg = W2; ld = 2048; k0 = (i - 64) * BK; }

        __half* ad = As + s * A_TILE;
        __half* bd = Bs + s * B_TILE;
#pragma unroll
        for (int j = 0; j < 2; ++j) {
            const int idx = tid + j * 256;
            const int row = idx >> 2;
            const int ch  = idx & 3;
            const int swc = ch ^ (row & 3);
            cp16(ad + row * 32 + (swc << 3),
                 Aseg + (size_t)(bm + row) * ld + k0 + (ch << 3));
        }
#pragma unroll
        for (int j = 0; j < 2; ++j) {
            const int idx = tid + j * 256;
            const int row = idx >> 2;
            const int ch  = idx & 3;
            const int swc = ch ^ (row & 3);
            cp16(bd + row * 32 + (swc << 3),
                 Wseg + (size_t)(bn + row) * ld + k0 + (ch << 3));
        }
        cp_commit();
    };

    issue(0); issue(1); issue(2);

    for (int i = 0; i < NCHUNK; ++i) {
        cp_wait2();
        __syncthreads();
        if (i + 3 < NCHUNK) issue(i + 3);

        const int buf = i & 3;
        const __half* A0 = As + buf * A_TILE + (wm * 64) * 32;
        const __half* B0 = Bs + buf * B_TILE + (wn * 32) * 32;

        uint4 bv[4];
#pragma unroll
        for (int nf = 0; nf < 4; ++nf)
            bv[nf] = *(const uint4*)(B0 + (nf * 8 + g) * 32 + loff);

#pragma unroll
        for (int mf = 0; mf < 4; ++mf) {
            const uint4 a0 = *(const uint4*)(A0 + (mf * 16 + g) * 32 + loff);
            const uint4 a1 = *(const uint4*)(A0 + (mf * 16 + g + 8) * 32 + loff);
#pragma unroll
            for (int nf = 0; nf < 4; ++nf)
                mma_f16(acc[mf][nf], a0.x, a1.x, a0.y, a1.y, bv[nf].x, bv[nf].y);
#pragma unroll
            for (int nf = 0; nf < 4; ++nf)
                mma_f16(acc[mf][nf], a0.z, a1.z, a0.w, a1.w, bv[nf].z, bv[nf].w);
        }
    }

    // ---- epilogue ----
    const bool is_r = (bn < 1024);
    const float* bias = (mode == 2) ? bias_a : (is_r ? bias_a : bias_b - 1024);

#pragma unroll
    for (int mf = 0; mf < 4; ++mf) {
#pragma unroll
        for (int nf = 0; nf < 4; ++nf) {
            const int n = bn + wn * 32 + nf * 8 + 2 * tg;
            const float2 bi = *(const float2*)(bias + n);
#pragma unroll
            for (int half = 0; half < 2; ++half) {
                const int m = bm + wm * 64 + mf * 16 + g + half * 8;
                float v0 = acc[mf][nf][2 * half + 0] + bi.x;
                float v1 = acc[mf][nf][2 * half + 1] + bi.y;
                if (mode == 0) {
                    if (is_r) {
                        const size_t idx = (size_t)m * HID + n;
                        const float2 hp = *(const float2*)(hprev + idx);
                        *(__half2*)(out_h + idx) =
                            __floats2half2_rn(fsigmoid(v0) * hp.x, fsigmoid(v1) * hp.y);
                    } else {
                        const size_t idx = (size_t)m * HID + (n - 1024);
                        float2 o;
                        o.x = fsigmoid(v0);
                        o.y = fsigmoid(v1);
                        *(float2*)(out_f + idx) = o;
                    }
                } else {
                    const size_t idx = (size_t)m * HID + n;
                    const float2 hp = *(const float2*)(hprev + idx);
                    const float2 zz = *(const float2*)(zbuf + idx);
                    float2 o;
                    o.x = fmaf(zz.x, ftanh(v0) - hp.x, hp.x);
                    o.y = fmaf(zz.y, ftanh(v1) - hp.y, hp.y);
                    *(float2*)(out_f + idx) = o;
                }
            }
        }
    }
}

extern "C" void kernel_launch(void* const* d_in, const int* in_sizes, int n_in,
                              void* d_out, int out_size)
{
    const float* x     = (const float*)d_in[0];
    const float* hprev = (const float*)d_in[1];
    const float* c     = (const float*)d_in[2];
    const float* Wh    = (const float*)d_in[3];
    const float* Wz    = (const float*)d_in[4];
    const float* Wr    = (const float*)d_in[5];
    const float* Uh    = (const float*)d_in[6];
    const float* Uz    = (const float*)d_in[7];
    const float* Ur    = (const float*)d_in[8];
    const float* Ch    = (const float*)d_in[9];
    const float* Cz    = (const float*)d_in[10];
    const float* Cr    = (const float*)d_in[11];
    const float* bh    = (const float*)d_in[12];
    const float* bz    = (const float*)d_in[13];
    const float* br    = (const float*)d_in[14];
    float* out = (float*)d_out;

    __half *x2, *h2, *c2, *rh2, *w2;
    float *z_p;
    cudaGetSymbolAddress((void**)&x2,  g_x2);
    cudaGetSymbolAddress((void**)&h2,  g_h2);
    cudaGetSymbolAddress((void**)&c2,  g_c2);
    cudaGetSymbolAddress((void**)&rh2, g_rh2);
    cudaGetSymbolAddress((void**)&z_p, g_z);
    cudaGetSymbolAddress((void**)&w2,  g_w2);

    const size_t M1 = (size_t)1024 * 1024;
    // stacked rz weights + h weights
    __half* rzW = w2;                 // [2048,1024]: Wr rows 0-1023, Wz rows 1024-2047
    __half* rzU = w2 + 2 * M1;        // [2048,1024]
    __half* rzC = w2 + 4 * M1;        // [2048,2048]
    __half* hW  = w2 + 8 * M1;        // [1024,1024]
    __half* hU  = w2 + 9 * M1;
    __half* hC  = w2 + 10 * M1;       // [1024,2048]

    // ---- one conversion launch, 12 segments ----
    CvtSegs segs;
    const float* srcs[NSEG] = { x, hprev, c,
                                Wr, Wz, Ur, Uz, Cr, Cz,
                                Wh, Uh, Ch };
    __half* dsts[NSEG] = { x2, h2, c2,
                           rzW, rzW + M1, rzU, rzU + M1, rzC, rzC + 2 * M1,
                           hW, hU, hC };
    const size_t cnts[NSEG] = { (size_t)BATCH * 1024, (size_t)BATCH * 1024, (size_t)BATCH * 2048,
                                M1, M1, M1, M1, 2 * M1, 2 * M1,
                                M1, M1, 2 * M1 };
    int off = 0;
    for (int s = 0; s < NSEG; ++s) {
        segs.src[s] = (const float4*)srcs[s];
        segs.dst[s] = (uint2*)dsts[s];
        segs.off[s] = off;
        off += (int)(cnts[s] / 4);
    }
    segs.off[NSEG] = off;
    cvt_all_kernel<<<2960, 256>>>(segs);

    cudaFuncSetAttribute(gate_mma_kernel,
                         cudaFuncAttributeMaxDynamicSharedMemorySize, SMEM_BYTES);

    const dim3 block(256);

    // fused r+z: N = 2048, grid (16, 64) = 1024 CTAs
    gate_mma_kernel<<<dim3(2048 / BN, BATCH / BM), block, SMEM_BYTES>>>(
        x2, h2, c2, rzW, rzU, rzC, br, bz, hprev, nullptr, rh2, z_p, 0);
    // h gate: N = 1024, grid (8, 64)
    gate_mma_kernel<<<dim3(HID / BN, BATCH / BM), block, SMEM_BYTES>>>(
        x2, rh2, c2, hW, hU, hC, bh, nullptr, hprev, z_p, nullptr, out, 2);
}